// round 4
// baseline (speedup 1.0000x reference)
#include <cuda_runtime.h>

#define NB 16
#define MM 1024
#define DD 64
#define HH 4
#define NEG 0.2f

// Scratch (allocation-free rule: __device__ globals)
__device__ float g_K[NB*HH*MM*DD];
__device__ float g_Q[NB*HH*MM*DD];
__device__ float g_V[NB*HH*MM*DD];
__device__ float g_dx[NB*MM*HH*DD];

// ---------------------------------------------------------------------------
// Kernel 1: per-head K/Q/V projections.  out[n,h,m,e] = x[n,m,:].W[h,e,:] + b
// grid (M/64, 3*H, N), block (16,16); thread owns 4x4 microtile,
// columns strided by 16 for conflict-free smem reads (pad 65).
// ---------------------------------------------------------------------------
__global__ __launch_bounds__(256) void qkv_kernel(
    const float* __restrict__ x,
    const float* __restrict__ Wk, const float* __restrict__ bk,
    const float* __restrict__ Wq, const float* __restrict__ bq,
    const float* __restrict__ Wv, const float* __restrict__ bv)
{
    __shared__ float xs[64*64];   // [64][64] (broadcast + float4 reads)
    __shared__ float Ws[64*65];   // [64][65] padded (strided reads)
    int n = blockIdx.z;
    int which = blockIdx.y / HH;
    int h = blockIdx.y % HH;
    int mtile = blockIdx.x * 64;
    const float* W; const float* bias; float* out;
    if (which == 0)      { W = Wk; bias = bk; out = g_K; }
    else if (which == 1) { W = Wq; bias = bq; out = g_Q; }
    else                 { W = Wv; bias = bv; out = g_V; }
    int tx = threadIdx.x, ty = threadIdx.y;
    int tid = ty*16 + tx;
    const float* xg = x + (size_t)(n*MM + mtile)*DD;
    const float* wg = W + h*DD*DD;
    #pragma unroll
    for (int r = 0; r < 16; r++) {
        int l = r*256 + tid;
        xs[l] = xg[l];
        Ws[(l>>6)*65 + (l&63)] = wg[l];
    }
    __syncthreads();
    float acc[4][4] = {};
    int ty4 = ty*4;
    #pragma unroll 4
    for (int d = 0; d < 64; d += 4) {
        float4 xr[4];
        #pragma unroll
        for (int a = 0; a < 4; a++)
            xr[a] = *(const float4*)&xs[(ty4+a)*64 + d];
        #pragma unroll
        for (int b = 0; b < 4; b++) {
            const float* wp = &Ws[(b*16+tx)*65 + d];
            float w0 = wp[0], w1 = wp[1], w2 = wp[2], w3 = wp[3];
            #pragma unroll
            for (int a = 0; a < 4; a++) {
                acc[a][b] = fmaf(xr[a].x, w0, acc[a][b]);
                acc[a][b] = fmaf(xr[a].y, w1, acc[a][b]);
                acc[a][b] = fmaf(xr[a].z, w2, acc[a][b]);
                acc[a][b] = fmaf(xr[a].w, w3, acc[a][b]);
            }
        }
    }
    float* og = out + ((size_t)(n*HH + h)*MM + mtile)*DD;
    #pragma unroll
    for (int b = 0; b < 4; b++) {
        float bb = bias[h*DD + b*16 + tx];
        #pragma unroll
        for (int a = 0; a < 4; a++)
            og[(ty4+a)*DD + b*16 + tx] = acc[a][b] + bb;
    }
}

// ---------------------------------------------------------------------------
// Kernel 2: flash-style attention per (n,h,i-tile of 64).
// scores s[i,j] = K_i.Q_j -> leaky -> online softmax over j -> .V
// epilogue: leaky(agg/l) - x, written to g_dx in (N, M, H*D) layout.
// ---------------------------------------------------------------------------
#define ATTN_SMEM ((64*64 + 64*65 + 64*65 + 64*68) * 4)

__global__ __launch_bounds__(256) void attn_kernel(const float* __restrict__ x)
{
    extern __shared__ float sm[];
    float* Ks = sm;              // [64][64]  (broadcast, float4 over d)
    float* Qs = Ks + 64*64;      // [64][65]  (strided cols, pad 65)
    float* Vs = Qs + 64*65;      // [64][65]
    float* Ps = Vs + 64*65;      // [64][68]  (broadcast, float4 over j)
    int n = blockIdx.z, h = blockIdx.y;
    int itile = blockIdx.x * 64;
    int tx = threadIdx.x, ty = threadIdx.y;
    int tid = ty*16 + tx;
    int ty4 = ty*4;
    const float* Kg = g_K + ((size_t)(n*HH + h)*MM + itile)*DD;
    const float* Qb = g_Q + (size_t)(n*HH + h)*MM*DD;
    const float* Vb = g_V + (size_t)(n*HH + h)*MM*DD;
    #pragma unroll
    for (int r = 0; r < 16; r++) {
        int l = r*256 + tid;
        Ks[l] = Kg[l];
    }
    float o[4][4] = {};
    float mrow[4], lrow[4];
    #pragma unroll
    for (int a = 0; a < 4; a++) { mrow[a] = -1e30f; lrow[a] = 0.f; }

    for (int jt = 0; jt < 16; jt++) {
        __syncthreads();                       // protect Qs/Vs (and Ks 1st iter)
        const float* qg = Qb + (size_t)jt*64*DD;
        const float* vg = Vb + (size_t)jt*64*DD;
        #pragma unroll
        for (int r = 0; r < 16; r++) {
            int l = r*256 + tid;
            int row = l>>6, col = l&63;
            Qs[row*65+col] = qg[l];
            Vs[row*65+col] = vg[l];
        }
        __syncthreads();
        // ---- S = K_tile . Q_tile^T ----
        float s[4][4] = {};
        #pragma unroll 4
        for (int d = 0; d < 64; d += 4) {
            float4 kr[4];
            #pragma unroll
            for (int a = 0; a < 4; a++)
                kr[a] = *(const float4*)&Ks[(ty4+a)*64 + d];
            #pragma unroll
            for (int b = 0; b < 4; b++) {
                const float* qp = &Qs[(b*16+tx)*65 + d];
                float q0 = qp[0], q1 = qp[1], q2 = qp[2], q3 = qp[3];
                #pragma unroll
                for (int a = 0; a < 4; a++) {
                    s[a][b] = fmaf(kr[a].x, q0, s[a][b]);
                    s[a][b] = fmaf(kr[a].y, q1, s[a][b]);
                    s[a][b] = fmaf(kr[a].z, q2, s[a][b]);
                    s[a][b] = fmaf(kr[a].w, q3, s[a][b]);
                }
            }
        }
        // ---- leaky relu + online softmax (stats replicated in 16-lane row group) ----
        #pragma unroll
        for (int a = 0; a < 4; a++) {
            #pragma unroll
            for (int b = 0; b < 4; b++)
                s[a][b] = s[a][b] > 0.f ? s[a][b] : NEG*s[a][b];
            float tm = fmaxf(fmaxf(s[a][0], s[a][1]), fmaxf(s[a][2], s[a][3]));
            #pragma unroll
            for (int off = 8; off >= 1; off >>= 1)
                tm = fmaxf(tm, __shfl_xor_sync(0xffffffffu, tm, off));
            float nm = fmaxf(mrow[a], tm);
            float corr = __expf(mrow[a] - nm);
            float rs = 0.f;
            #pragma unroll
            for (int b = 0; b < 4; b++) {
                s[a][b] = __expf(s[a][b] - nm);
                rs += s[a][b];
            }
            #pragma unroll
            for (int off = 8; off >= 1; off >>= 1)
                rs += __shfl_xor_sync(0xffffffffu, rs, off);
            lrow[a] = lrow[a]*corr + rs;
            mrow[a] = nm;
            #pragma unroll
            for (int b = 0; b < 4; b++) {
                o[a][b] *= corr;
                Ps[(ty4+a)*68 + b*16 + tx] = s[a][b];
            }
        }
        __syncthreads();
        // ---- O += P . V_tile ----
        #pragma unroll 4
        for (int j = 0; j < 64; j += 4) {
            float4 pr[4];
            #pragma unroll
            for (int a = 0; a < 4; a++)
                pr[a] = *(const float4*)&Ps[(ty4+a)*68 + j];
            #pragma unroll
            for (int b = 0; b < 4; b++) {
                int col = b*16 + tx;
                float v0 = Vs[(j+0)*65 + col];
                float v1 = Vs[(j+1)*65 + col];
                float v2 = Vs[(j+2)*65 + col];
                float v3 = Vs[(j+3)*65 + col];
                #pragma unroll
                for (int a = 0; a < 4; a++) {
                    o[a][b] = fmaf(pr[a].x, v0, o[a][b]);
                    o[a][b] = fmaf(pr[a].y, v1, o[a][b]);
                    o[a][b] = fmaf(pr[a].z, v2, o[a][b]);
                    o[a][b] = fmaf(pr[a].w, v3, o[a][b]);
                }
            }
        }
    }
    __syncthreads();
    // epilogue: reuse Qs for the x tile
    const float* xg = x + (size_t)(n*MM + itile)*DD;
    #pragma unroll
    for (int r = 0; r < 16; r++) {
        int l = r*256 + tid;
        Qs[(l>>6)*65 + (l&63)] = xg[l];
    }
    __syncthreads();
    float* og = g_dx + (size_t)(n*MM + itile)*(HH*DD) + h*DD;
    #pragma unroll
    for (int a = 0; a < 4; a++) {
        float inv = 1.f / lrow[a];
        #pragma unroll
        for (int b = 0; b < 4; b++) {
            float v = o[a][b] * inv;
            v = v > 0.f ? v : NEG*v;
            v -= Qs[(ty4+a)*65 + b*16 + tx];
            og[(ty4+a)*(HH*DD) + b*16 + tx] = v;
        }
    }
}

// ---------------------------------------------------------------------------
// Kernel 3: decoder.  out[row,e] = g_dx[row,:].Wdec[e,:] + bdec[e]
// 16384 rows, block = 64 rows; full 64x256 Wdec + dx tile in smem.
// ---------------------------------------------------------------------------
#define DEC_SMEM ((64*256 + 64*257) * 4)

__global__ __launch_bounds__(256) void dec_kernel(
    const float* __restrict__ Wdec, const float* __restrict__ bdec,
    float* __restrict__ out)
{
    extern __shared__ float sm[];
    float* ds = sm;              // [64][256] (broadcast + float4)
    float* Ws = ds + 64*256;     // [64][257] padded (strided reads)
    int row0 = blockIdx.x * 64;
    int tx = threadIdx.x, ty = threadIdx.y;
    int tid = ty*16 + tx;
    #pragma unroll
    for (int r = 0; r < 64; r++) {
        int l = r*256 + tid;
        ds[l] = g_dx[(size_t)row0*256 + l];
        Ws[(l>>8)*257 + (l&255)] = Wdec[l];
    }
    __syncthreads();
    float acc[4][4] = {};
    int ty4 = ty*4;
    #pragma unroll 4
    for (int c = 0; c < 256; c += 4) {
        float4 dr[4];
        #pragma unroll
        for (int a = 0; a < 4; a++)
            dr[a] = *(const float4*)&ds[(ty4+a)*256 + c];
        #pragma unroll
        for (int b = 0; b < 4; b++) {
            const float* wp = &Ws[(b*16+tx)*257 + c];
            float w0 = wp[0], w1 = wp[1], w2 = wp[2], w3 = wp[3];
            #pragma unroll
            for (int a = 0; a < 4; a++) {
                acc[a][b] = fmaf(dr[a].x, w0, acc[a][b]);
                acc[a][b] = fmaf(dr[a].y, w1, acc[a][b]);
                acc[a][b] = fmaf(dr[a].z, w2, acc[a][b]);
                acc[a][b] = fmaf(dr[a].w, w3, acc[a][b]);
            }
        }
    }
    #pragma unroll
    for (int b = 0; b < 4; b++) {
        float bb = bdec[b*16 + tx];
        #pragma unroll
        for (int a = 0; a < 4; a++)
            out[(size_t)(row0 + ty4 + a)*DD + b*16 + tx] = acc[a][b] + bb;
    }
}

// ---------------------------------------------------------------------------
extern "C" void kernel_launch(void* const* d_in, const int* in_sizes, int n_in,
                              void* d_out, int out_size)
{
    const float* x    = (const float*)d_in[0];
    // d_in[1] = edge (unused)
    const float* Wk   = (const float*)d_in[2];
    const float* bk   = (const float*)d_in[3];
    const float* Wq   = (const float*)d_in[4];
    const float* bq   = (const float*)d_in[5];
    const float* Wv   = (const float*)d_in[6];
    const float* bv   = (const float*)d_in[7];
    const float* Wdec = (const float*)d_in[8];
    const float* bdec = (const float*)d_in[9];
    float* out = (float*)d_out;

    // >48KB dynamic smem opt-in (idempotent; not a stream op, capture-safe)
    cudaFuncSetAttribute(attn_kernel, cudaFuncAttributeMaxDynamicSharedMemorySize, ATTN_SMEM);
    cudaFuncSetAttribute(dec_kernel,  cudaFuncAttributeMaxDynamicSharedMemorySize, DEC_SMEM);

    dim3 blk(16, 16);
    qkv_kernel<<<dim3(MM/64, 3*HH, NB), blk>>>(x, Wk, bk, Wq, bq, Wv, bv);
    attn_kernel<<<dim3(MM/64, HH, NB), blk, ATTN_SMEM>>>(x);
    dec_kernel<<<NB*MM/64, blk, DEC_SMEM>>>(Wdec, bdec, out);
}

// round 5
// speedup vs baseline: 2.1984x; 2.1984x over previous
#include <cuda_runtime.h>

#define NB 16
#define MM 1024
#define DD 64
#define HH 4
#define NEG 0.2f

// Scratch (allocation-free rule: __device__ globals)
__device__ float g_K[NB*HH*MM*DD];
__device__ float g_Q[NB*HH*MM*DD];   // stored pre-rounded to tf32
__device__ float g_V[NB*HH*MM*DD];   // stored pre-rounded to tf32
__device__ float g_dx[NB*MM*HH*DD];

__device__ __forceinline__ unsigned f2tf32(float f) {
    unsigned u;
    asm("cvt.rna.tf32.f32 %0, %1;" : "=r"(u) : "f"(f));
    return u;
}

__device__ __forceinline__ void mma_tf32(float& d0, float& d1, float& d2, float& d3,
                                         unsigned a0, unsigned a1, unsigned a2, unsigned a3,
                                         unsigned b0, unsigned b1) {
    asm volatile("mma.sync.aligned.m16n8k8.row.col.f32.tf32.tf32.f32 "
                 "{%0,%1,%2,%3}, {%4,%5,%6,%7}, {%8,%9}, {%0,%1,%2,%3};"
                 : "+f"(d0), "+f"(d1), "+f"(d2), "+f"(d3)
                 : "r"(a0), "r"(a1), "r"(a2), "r"(a3), "r"(b0), "r"(b1));
}

__device__ __forceinline__ void cp16(unsigned dst_smem, const void* src) {
    asm volatile("cp.async.cg.shared.global [%0], [%1], 16;" :: "r"(dst_smem), "l"(src));
}

// ---------------------------------------------------------------------------
// Kernel 1: per-head K/Q/V projections (fp32 SIMT; only 1.6 GF).
// Q and V outputs are pre-rounded to tf32 (rna) so the attention kernel can
// feed them to HMMA.TF32 without per-use cvt.
// ---------------------------------------------------------------------------
__global__ __launch_bounds__(256) void qkv_kernel(
    const float* __restrict__ x,
    const float* __restrict__ Wk, const float* __restrict__ bk,
    const float* __restrict__ Wq, const float* __restrict__ bq,
    const float* __restrict__ Wv, const float* __restrict__ bv)
{
    __shared__ float xs[64*64];
    __shared__ float Ws[64*65];
    int n = blockIdx.z;
    int which = blockIdx.y / HH;
    int h = blockIdx.y % HH;
    int mtile = blockIdx.x * 64;
    const float* W; const float* bias; float* out;
    if (which == 0)      { W = Wk; bias = bk; out = g_K; }
    else if (which == 1) { W = Wq; bias = bq; out = g_Q; }
    else                 { W = Wv; bias = bv; out = g_V; }
    int tx = threadIdx.x, ty = threadIdx.y;
    int tid = ty*16 + tx;
    const float* xg = x + (size_t)(n*MM + mtile)*DD;
    const float* wg = W + h*DD*DD;
    #pragma unroll
    for (int r = 0; r < 16; r++) {
        int l = r*256 + tid;
        xs[l] = xg[l];
        Ws[(l>>6)*65 + (l&63)] = wg[l];
    }
    __syncthreads();
    float acc[4][4] = {};
    int ty4 = ty*4;
    #pragma unroll 4
    for (int d = 0; d < 64; d += 4) {
        float4 xr[4];
        #pragma unroll
        for (int a = 0; a < 4; a++)
            xr[a] = *(const float4*)&xs[(ty4+a)*64 + d];
        #pragma unroll
        for (int b = 0; b < 4; b++) {
            const float* wp = &Ws[(b*16+tx)*65 + d];
            float w0 = wp[0], w1 = wp[1], w2 = wp[2], w3 = wp[3];
            #pragma unroll
            for (int a = 0; a < 4; a++) {
                acc[a][b] = fmaf(xr[a].x, w0, acc[a][b]);
                acc[a][b] = fmaf(xr[a].y, w1, acc[a][b]);
                acc[a][b] = fmaf(xr[a].z, w2, acc[a][b]);
                acc[a][b] = fmaf(xr[a].w, w3, acc[a][b]);
            }
        }
    }
    float* og = out + ((size_t)(n*HH + h)*MM + mtile)*DD;
    #pragma unroll
    for (int b = 0; b < 4; b++) {
        float bb = bias[h*DD + b*16 + tx];
        #pragma unroll
        for (int a = 0; a < 4; a++) {
            float v = acc[a][b] + bb;
            if (which != 0) v = __uint_as_float(f2tf32(v));  // pre-round Q, V
            og[(ty4+a)*DD + b*16 + tx] = v;
        }
    }
}

// ---------------------------------------------------------------------------
// Kernel 2: TF32 tensor-core flash attention.
// grid (M/128, H, N), block 256 (8 warps). Warp w owns rows itile+w*16..+15.
// S = K.Q^T (m16n8k8 tf32), leaky, online softmax, O += P.V, epilogue to g_dx.
// smem: Q[2][64][68], V[2][64][72] (cp.async double buffer), P[128][68].
// ---------------------------------------------------------------------------
#define QSTR 68
#define VSTR 72
#define PSTR 68
#define ATTN2_SMEM ((2*64*QSTR + 2*64*VSTR + 128*PSTR) * 4)

__global__ __launch_bounds__(256, 2) void attn_tc(const float* __restrict__ x)
{
    extern __shared__ float sm[];
    float* Qs[2] = { sm, sm + 64*QSTR };
    float* Vs[2] = { sm + 2*64*QSTR, sm + 2*64*QSTR + 64*VSTR };
    float* Ps    = sm + 2*64*QSTR + 2*64*VSTR;   // [128][68], per-warp slice

    int n = blockIdx.z, h = blockIdx.y;
    int itile = blockIdx.x * 128;
    int tid = threadIdx.x;
    int warp = tid >> 5, lane = tid & 31;
    int qr = lane >> 2, qc = lane & 3;

    const float* Kg = g_K + (size_t)(n*HH + h)*MM*DD;
    const float* Qb = g_Q + (size_t)(n*HH + h)*MM*DD;
    const float* Vb = g_V + (size_t)(n*HH + h)*MM*DD;

    int r0 = itile + warp*16 + qr;   // global rows r0, r0+8 for this thread

    // Hoist K A-fragments for the whole j-loop (read once, cvt.rna)
    unsigned ka[8][4];
    #pragma unroll
    for (int kk = 0; kk < 8; kk++) {
        ka[kk][0] = f2tf32(Kg[(size_t)r0*DD     + kk*8 + qc    ]);
        ka[kk][1] = f2tf32(Kg[(size_t)(r0+8)*DD + kk*8 + qc    ]);
        ka[kk][2] = f2tf32(Kg[(size_t)r0*DD     + kk*8 + qc + 4]);
        ka[kk][3] = f2tf32(Kg[(size_t)(r0+8)*DD + kk*8 + qc + 4]);
    }

    float o[8][4] = {};
    float mr0 = -1e30f, mr1 = -1e30f, lr0 = 0.f, lr1 = 0.f;

    unsigned qbase[2], vbase[2];
    qbase[0] = (unsigned)__cvta_generic_to_shared(Qs[0]);
    qbase[1] = (unsigned)__cvta_generic_to_shared(Qs[1]);
    vbase[0] = (unsigned)__cvta_generic_to_shared(Vs[0]);
    vbase[1] = (unsigned)__cvta_generic_to_shared(Vs[1]);

    // stage tile 0 into buffer 0
    #pragma unroll
    for (int k = 0; k < 4; k++) {
        int l = 4*tid + 1024*k;          // float index in 64x64 tile
        int row = l >> 6, col = l & 63;
        cp16(qbase[0] + (row*QSTR + col)*4, Qb + l);
        cp16(vbase[0] + (row*VSTR + col)*4, Vb + l);
    }
    asm volatile("cp.async.commit_group;");

    for (int jt = 0; jt < 16; jt++) {
        int buf = jt & 1;
        if (jt < 15) {
            const float* qg = Qb + (size_t)(jt+1)*64*DD;
            const float* vg = Vb + (size_t)(jt+1)*64*DD;
            int nb = buf ^ 1;
            #pragma unroll
            for (int k = 0; k < 4; k++) {
                int l = 4*tid + 1024*k;
                int row = l >> 6, col = l & 63;
                cp16(qbase[nb] + (row*QSTR + col)*4, qg + l);
                cp16(vbase[nb] + (row*VSTR + col)*4, vg + l);
            }
            asm volatile("cp.async.commit_group;");
            asm volatile("cp.async.wait_group 1;");
        } else {
            asm volatile("cp.async.wait_group 0;");
        }
        __syncthreads();

        const float* Qc = Qs[buf];
        const float* Vc = Vs[buf];

        // ---- S = K . Q^T ----
        float s[8][4];
        #pragma unroll
        for (int nt = 0; nt < 8; nt++) {
            s[nt][0] = s[nt][1] = s[nt][2] = s[nt][3] = 0.f;
            #pragma unroll
            for (int kk = 0; kk < 8; kk++) {
                const float* qp = &Qc[(nt*8 + qr)*QSTR + kk*8 + qc];
                unsigned b0 = __float_as_uint(qp[0]);   // pre-rounded tf32
                unsigned b1 = __float_as_uint(qp[4]);
                mma_tf32(s[nt][0], s[nt][1], s[nt][2], s[nt][3],
                         ka[kk][0], ka[kk][1], ka[kk][2], ka[kk][3], b0, b1);
            }
        }

        // ---- leaky relu + online softmax (rows r0 -> .x/.y, r1 -> .z/.w) ----
        float m0 = -1e30f, m1 = -1e30f;
        #pragma unroll
        for (int nt = 0; nt < 8; nt++) {
            #pragma unroll
            for (int c = 0; c < 4; c++)
                s[nt][c] = s[nt][c] > 0.f ? s[nt][c] : NEG*s[nt][c];
            m0 = fmaxf(m0, fmaxf(s[nt][0], s[nt][1]));
            m1 = fmaxf(m1, fmaxf(s[nt][2], s[nt][3]));
        }
        m0 = fmaxf(m0, __shfl_xor_sync(0xffffffffu, m0, 1));
        m0 = fmaxf(m0, __shfl_xor_sync(0xffffffffu, m0, 2));
        m1 = fmaxf(m1, __shfl_xor_sync(0xffffffffu, m1, 1));
        m1 = fmaxf(m1, __shfl_xor_sync(0xffffffffu, m1, 2));
        float nm0 = fmaxf(mr0, m0), nm1 = fmaxf(mr1, m1);
        float c0 = __expf(mr0 - nm0), c1 = __expf(mr1 - nm1);
        mr0 = nm0; mr1 = nm1;
        float a0 = 0.f, a1 = 0.f;
        float* pw0 = &Ps[(warp*16 + qr)*PSTR];
        float* pw1 = pw0 + 8*PSTR;
        #pragma unroll
        for (int nt = 0; nt < 8; nt++) {
            float e0 = __expf(s[nt][0] - nm0);
            float e1 = __expf(s[nt][1] - nm0);
            float e2 = __expf(s[nt][2] - nm1);
            float e3 = __expf(s[nt][3] - nm1);
            a0 += e0 + e1; a1 += e2 + e3;
            *(float2*)&pw0[nt*8 + 2*qc] = make_float2(e0, e1);
            *(float2*)&pw1[nt*8 + 2*qc] = make_float2(e2, e3);
            o[nt][0] *= c0; o[nt][1] *= c0; o[nt][2] *= c1; o[nt][3] *= c1;
        }
        a0 += __shfl_xor_sync(0xffffffffu, a0, 1);
        a0 += __shfl_xor_sync(0xffffffffu, a0, 2);
        a1 += __shfl_xor_sync(0xffffffffu, a1, 1);
        a1 += __shfl_xor_sync(0xffffffffu, a1, 2);
        lr0 = lr0*c0 + a0;
        lr1 = lr1*c1 + a1;

        __syncwarp();   // P slice is per-warp: warp-level fence suffices

        // ---- O += P . V ----
        unsigned pa[8][4];
        #pragma unroll
        for (int kk = 0; kk < 8; kk++) {
            const float* pb = &Ps[(warp*16 + qr)*PSTR + kk*8 + qc];
            pa[kk][0] = f2tf32(pb[0]);
            pa[kk][1] = f2tf32(pb[8*PSTR]);
            pa[kk][2] = f2tf32(pb[4]);
            pa[kk][3] = f2tf32(pb[8*PSTR + 4]);
        }
        #pragma unroll
        for (int nt = 0; nt < 8; nt++) {
            #pragma unroll
            for (int kk = 0; kk < 8; kk++) {
                unsigned b0 = __float_as_uint(Vc[(kk*8 + qc    )*VSTR + nt*8 + qr]);
                unsigned b1 = __float_as_uint(Vc[(kk*8 + qc + 4)*VSTR + nt*8 + qr]);
                mma_tf32(o[nt][0], o[nt][1], o[nt][2], o[nt][3],
                         pa[kk][0], pa[kk][1], pa[kk][2], pa[kk][3], b0, b1);
            }
        }
        __syncthreads();   // before next iter's cp.async overwrites buf^1
    }

    // ---- epilogue: leaky(o/l) - x -> g_dx (N, M, H*D) ----
    float inv0 = 1.f / lr0, inv1 = 1.f / lr1;
    size_t gm0 = (size_t)(n*MM + r0);
    size_t gm1 = gm0 + 8;
    const float* x0 = x + gm0*DD;
    const float* x1 = x + gm1*DD;
    float* d0 = g_dx + gm0*(HH*DD) + h*DD;
    float* d1 = g_dx + gm1*(HH*DD) + h*DD;
    #pragma unroll
    for (int nt = 0; nt < 8; nt++) {
        int cb = nt*8 + 2*qc;
        float2 xv0 = *(const float2*)&x0[cb];
        float2 xv1 = *(const float2*)&x1[cb];
        float v00 = o[nt][0]*inv0; v00 = (v00 > 0.f ? v00 : NEG*v00) - xv0.x;
        float v01 = o[nt][1]*inv0; v01 = (v01 > 0.f ? v01 : NEG*v01) - xv0.y;
        float v10 = o[nt][2]*inv1; v10 = (v10 > 0.f ? v10 : NEG*v10) - xv1.x;
        float v11 = o[nt][3]*inv1; v11 = (v11 > 0.f ? v11 : NEG*v11) - xv1.y;
        *(float2*)&d0[cb] = make_float2(v00, v01);
        *(float2*)&d1[cb] = make_float2(v10, v11);
    }
}

// ---------------------------------------------------------------------------
// Kernel 3: decoder (fp32 SIMT; 0.54 GF).
// ---------------------------------------------------------------------------
#define DEC_SMEM ((64*256 + 64*257) * 4)

__global__ __launch_bounds__(256) void dec_kernel(
    const float* __restrict__ Wdec, const float* __restrict__ bdec,
    float* __restrict__ out)
{
    extern __shared__ float sm[];
    float* ds = sm;
    float* Ws = ds + 64*256;
    int row0 = blockIdx.x * 64;
    int tx = threadIdx.x, ty = threadIdx.y;
    int tid = ty*16 + tx;
    #pragma unroll
    for (int r = 0; r < 64; r++) {
        int l = r*256 + tid;
        ds[l] = g_dx[(size_t)row0*256 + l];
        Ws[(l>>8)*257 + (l&255)] = Wdec[l];
    }
    __syncthreads();
    float acc[4][4] = {};
    int ty4 = ty*4;
    #pragma unroll 4
    for (int c = 0; c < 256; c += 4) {
        float4 dr[4];
        #pragma unroll
        for (int a = 0; a < 4; a++)
            dr[a] = *(const float4*)&ds[(ty4+a)*256 + c];
        #pragma unroll
        for (int b = 0; b < 4; b++) {
            const float* wp = &Ws[(b*16+tx)*257 + c];
            float w0 = wp[0], w1 = wp[1], w2 = wp[2], w3 = wp[3];
            #pragma unroll
            for (int a = 0; a < 4; a++) {
                acc[a][b] = fmaf(dr[a].x, w0, acc[a][b]);
                acc[a][b] = fmaf(dr[a].y, w1, acc[a][b]);
                acc[a][b] = fmaf(dr[a].z, w2, acc[a][b]);
                acc[a][b] = fmaf(dr[a].w, w3, acc[a][b]);
            }
        }
    }
    #pragma unroll
    for (int b = 0; b < 4; b++) {
        float bb = bdec[b*16 + tx];
        #pragma unroll
        for (int a = 0; a < 4; a++)
            out[(size_t)(row0 + ty4 + a)*DD + b*16 + tx] = acc[a][b] + bb;
    }
}

// ---------------------------------------------------------------------------
extern "C" void kernel_launch(void* const* d_in, const int* in_sizes, int n_in,
                              void* d_out, int out_size)
{
    const float* x    = (const float*)d_in[0];
    // d_in[1] = edge (unused)
    const float* Wk   = (const float*)d_in[2];
    const float* bk   = (const float*)d_in[3];
    const float* Wq   = (const float*)d_in[4];
    const float* bq   = (const float*)d_in[5];
    const float* Wv   = (const float*)d_in[6];
    const float* bv   = (const float*)d_in[7];
    const float* Wdec = (const float*)d_in[8];
    const float* bdec = (const float*)d_in[9];
    float* out = (float*)d_out;

    cudaFuncSetAttribute(attn_tc,   cudaFuncAttributeMaxDynamicSharedMemorySize, ATTN2_SMEM);
    cudaFuncSetAttribute(dec_kernel, cudaFuncAttributeMaxDynamicSharedMemorySize, DEC_SMEM);

    dim3 blk(16, 16);
    qkv_kernel<<<dim3(MM/64, 3*HH, NB), blk>>>(x, Wk, bk, Wq, bq, Wv, bv);
    attn_tc<<<dim3(MM/128, HH, NB), 256, ATTN2_SMEM>>>(x);
    dec_kernel<<<NB*MM/64, blk, DEC_SMEM>>>(Wdec, bdec, out);
}

// round 6
// speedup vs baseline: 2.2072x; 1.0040x over previous
#include <cuda_runtime.h>

#define NB 16
#define MM 1024
#define DD 64
#define HH 4
#define NEG 0.2f

// Scratch (allocation-free rule: __device__ globals)
__device__ float g_K[NB*HH*MM*DD];   // [n,h,m,d]   fp32
__device__ float g_Q[NB*HH*MM*DD];   // [n,h,m,d']  tf32-rounded, d-permuted
__device__ float g_V[NB*HH*MM*DD];   // Vt [n,h,e,m'] tf32-rounded, transposed + j-permuted
__device__ float g_dx[NB*MM*HH*DD];

__device__ __forceinline__ unsigned f2tf32(float f) {
    unsigned u;
    asm("cvt.rna.tf32.f32 %0, %1;" : "=r"(u) : "f"(f));
    return u;
}

__device__ __forceinline__ void mma_tf32(float& d0, float& d1, float& d2, float& d3,
                                         unsigned a0, unsigned a1, unsigned a2, unsigned a3,
                                         unsigned b0, unsigned b1) {
    asm volatile("mma.sync.aligned.m16n8k8.row.col.f32.tf32.tf32.f32 "
                 "{%0,%1,%2,%3}, {%4,%5,%6,%7}, {%8,%9}, {%0,%1,%2,%3};"
                 : "+f"(d0), "+f"(d1), "+f"(d2), "+f"(d3)
                 : "r"(a0), "r"(a1), "r"(a2), "r"(a3), "r"(b0), "r"(b1));
}

__device__ __forceinline__ void cp16(unsigned dst_smem, const void* src) {
    asm volatile("cp.async.cg.shared.global [%0], [%1], 16;" :: "r"(dst_smem), "l"(src));
}

// d-permutation for B-frag float4 loads: d' = (d%4)*16 + d/4
__device__ __forceinline__ int dperm(int d) { return (d & 3)*16 + (d >> 2); }
// j-permutation matching the S c-frag column order: j = 8k+2q+r -> q*16 + 2k + r
__device__ __forceinline__ int jperm(int j) {
    return ((j >> 1) & 3)*16 + ((j >> 3) << 1) + (j & 1);
}

// ---------------------------------------------------------------------------
// Kernel 1: TF32 tensor-core K/Q/V projections with 3-term precision split.
// grid (M/128, 3*H, N), block 256 (8 warps, 16 rows each).
// Epilogue fuses the attn-friendly layouts: K normal, Q d-permuted+rounded,
// V transposed (Vt[e][m]) with j-permuted m + rounded.
// ---------------------------------------------------------------------------
__global__ __launch_bounds__(256, 2) void qkv_tc(
    const float* __restrict__ x,
    const float* __restrict__ Wk, const float* __restrict__ bk,
    const float* __restrict__ Wq, const float* __restrict__ bq,
    const float* __restrict__ Wv, const float* __restrict__ bv)
{
    __shared__ float Wh[64*68];
    __shared__ float Wl[64*68];
    int n = blockIdx.z;
    int which = blockIdx.y / HH;
    int h = blockIdx.y % HH;
    int mtile = blockIdx.x * 128;
    const float* W; const float* bias;
    if (which == 0)      { W = Wk; bias = bk; }
    else if (which == 1) { W = Wq; bias = bq; }
    else                 { W = Wv; bias = bv; }
    int tid = threadIdx.x;
    int warp = tid >> 5, lane = tid & 31;
    int qr = lane >> 2, qc = lane & 3;

    const float* wg = W + h*DD*DD;
    #pragma unroll
    for (int i = 0; i < 16; i++) {
        int l = i*256 + tid;
        int e = l >> 6, d = l & 63;
        float w = wg[l];
        unsigned hi = f2tf32(w);
        int idx = e*68 + dperm(d);
        Wh[idx] = __uint_as_float(hi);
        Wl[idx] = __uint_as_float(f2tf32(w - __uint_as_float(hi)));
    }
    __syncthreads();

    int r0 = mtile + warp*16 + qr;
    const float* xg0 = x + (size_t)(n*MM + r0)*DD;
    const float* xg1 = xg0 + 8*DD;

    // hoist x A-operands (raw fp32)
    float xa[4][8];
    #pragma unroll
    for (int kk = 0; kk < 8; kk++) {
        xa[0][kk] = xg0[kk*8 + qc];
        xa[1][kk] = xg1[kk*8 + qc];
        xa[2][kk] = xg0[kk*8 + qc + 4];
        xa[3][kk] = xg1[kk*8 + qc + 4];
    }

    float o[8][4] = {};
    #pragma unroll
    for (int kkp = 0; kkp < 4; kkp++) {
        unsigned ah0[4], al0[4], ah1[4], al1[4];
        #pragma unroll
        for (int i = 0; i < 4; i++) {
            float v0 = xa[i][2*kkp], v1 = xa[i][2*kkp+1];
            ah0[i] = f2tf32(v0); al0[i] = f2tf32(v0 - __uint_as_float(ah0[i]));
            ah1[i] = f2tf32(v1); al1[i] = f2tf32(v1 - __uint_as_float(ah1[i]));
        }
        #pragma unroll
        for (int nt = 0; nt < 8; nt++) {
            int row = (nt*8 + qr)*68 + qc*16 + 4*kkp;
            float4 fh = *(const float4*)&Wh[row];
            float4 fl = *(const float4*)&Wl[row];
            unsigned bh0 = __float_as_uint(fh.x), bh1 = __float_as_uint(fh.y);
            unsigned bl0 = __float_as_uint(fl.x), bl1 = __float_as_uint(fl.y);
            mma_tf32(o[nt][0],o[nt][1],o[nt][2],o[nt][3], ah0[0],ah0[1],ah0[2],ah0[3], bh0,bh1);
            mma_tf32(o[nt][0],o[nt][1],o[nt][2],o[nt][3], ah0[0],ah0[1],ah0[2],ah0[3], bl0,bl1);
            mma_tf32(o[nt][0],o[nt][1],o[nt][2],o[nt][3], al0[0],al0[1],al0[2],al0[3], bh0,bh1);
            unsigned ch0 = __float_as_uint(fh.z), ch1 = __float_as_uint(fh.w);
            unsigned cl0 = __float_as_uint(fl.z), cl1 = __float_as_uint(fl.w);
            mma_tf32(o[nt][0],o[nt][1],o[nt][2],o[nt][3], ah1[0],ah1[1],ah1[2],ah1[3], ch0,ch1);
            mma_tf32(o[nt][0],o[nt][1],o[nt][2],o[nt][3], ah1[0],ah1[1],ah1[2],ah1[3], cl0,cl1);
            mma_tf32(o[nt][0],o[nt][1],o[nt][2],o[nt][3], al1[0],al1[1],al1[2],al1[3], ch0,ch1);
        }
    }

    // epilogue
    size_t hb = (size_t)(n*HH + h);
    if (which == 0) {
        float* Ko = g_K + hb*MM*DD;
        #pragma unroll
        for (int nt = 0; nt < 8; nt++) {
            int c0 = nt*8 + 2*qc;
            float b0 = bias[h*DD + c0], b1 = bias[h*DD + c0 + 1];
            *(float2*)&Ko[(size_t)r0*DD + c0]     = make_float2(o[nt][0]+b0, o[nt][1]+b1);
            *(float2*)&Ko[(size_t)(r0+8)*DD + c0] = make_float2(o[nt][2]+b0, o[nt][3]+b1);
        }
    } else if (which == 1) {
        float* Qo = g_Q + hb*MM*DD;
        #pragma unroll
        for (int nt = 0; nt < 8; nt++) {
            int c0 = nt*8 + 2*qc;
            float b0 = bias[h*DD + c0], b1 = bias[h*DD + c0 + 1];
            int dp = dperm(c0);
            Qo[(size_t)r0*DD + dp]          = __uint_as_float(f2tf32(o[nt][0]+b0));
            Qo[(size_t)r0*DD + dp + 16]     = __uint_as_float(f2tf32(o[nt][1]+b1));
            Qo[(size_t)(r0+8)*DD + dp]      = __uint_as_float(f2tf32(o[nt][2]+b0));
            Qo[(size_t)(r0+8)*DD + dp + 16] = __uint_as_float(f2tf32(o[nt][3]+b1));
        }
    } else {
        float* Vt = g_V + hb*DD*MM;   // [e][m']
        int mp0 = (r0 & ~63) + jperm(r0 & 63);
        int mp1 = ((r0+8) & ~63) + jperm((r0+8) & 63);
        #pragma unroll
        for (int nt = 0; nt < 8; nt++) {
            int c0 = nt*8 + 2*qc;
            float b0 = bias[h*DD + c0], b1 = bias[h*DD + c0 + 1];
            Vt[(size_t)c0*MM     + mp0] = __uint_as_float(f2tf32(o[nt][0]+b0));
            Vt[(size_t)(c0+1)*MM + mp0] = __uint_as_float(f2tf32(o[nt][1]+b1));
            Vt[(size_t)c0*MM     + mp1] = __uint_as_float(f2tf32(o[nt][2]+b0));
            Vt[(size_t)(c0+1)*MM + mp1] = __uint_as_float(f2tf32(o[nt][3]+b1));
        }
    }
}

// ---------------------------------------------------------------------------
// Kernel 2: TF32 tensor-core flash attention, vectorized fragments.
// B-frags for S (Q) and PV (Vt) via LDS.128 from permuted layouts;
// PV A-frags come straight from the S accumulator registers (no P smem).
// smem: Q[2][64][68], Vt[2][64][68] cp.async double-buffered.
// ---------------------------------------------------------------------------
#define TSTR 68
#define ATTN2_SMEM ((4*64*TSTR) * 4)

__global__ __launch_bounds__(256, 2) void attn_tc(const float* __restrict__ x)
{
    extern __shared__ float sm[];
    float* Qs[2] = { sm, sm + 64*TSTR };
    float* Vs[2] = { sm + 2*64*TSTR, sm + 3*64*TSTR };

    int n = blockIdx.z, h = blockIdx.y;
    int itile = blockIdx.x * 128;
    int tid = threadIdx.x;
    int warp = tid >> 5, lane = tid & 31;
    int qr = lane >> 2, qc = lane & 3;

    const float* Kg = g_K + (size_t)(n*HH + h)*MM*DD;
    const float* Qb = g_Q + (size_t)(n*HH + h)*MM*DD;
    const float* Vb = g_V + (size_t)(n*HH + h)*DD*MM;   // Vt [e][m']

    int r0 = itile + warp*16 + qr;

    // Hoist K A-fragments for the whole j-loop
    unsigned ka[8][4];
    #pragma unroll
    for (int kk = 0; kk < 8; kk++) {
        ka[kk][0] = f2tf32(Kg[(size_t)r0*DD     + kk*8 + qc    ]);
        ka[kk][1] = f2tf32(Kg[(size_t)(r0+8)*DD + kk*8 + qc    ]);
        ka[kk][2] = f2tf32(Kg[(size_t)r0*DD     + kk*8 + qc + 4]);
        ka[kk][3] = f2tf32(Kg[(size_t)(r0+8)*DD + kk*8 + qc + 4]);
    }

    float o[8][4] = {};
    float mr0 = -1e30f, mr1 = -1e30f, lr0 = 0.f, lr1 = 0.f;

    unsigned qbase[2], vbase[2];
    qbase[0] = (unsigned)__cvta_generic_to_shared(Qs[0]);
    qbase[1] = (unsigned)__cvta_generic_to_shared(Qs[1]);
    vbase[0] = (unsigned)__cvta_generic_to_shared(Vs[0]);
    vbase[1] = (unsigned)__cvta_generic_to_shared(Vs[1]);

    // stage tile 0
    #pragma unroll
    for (int k = 0; k < 4; k++) {
        int l = 4*tid + 1024*k;
        int row = l >> 6, col = l & 63;
        cp16(qbase[0] + (row*TSTR + col)*4, Qb + (size_t)row*DD + col);
        cp16(vbase[0] + (row*TSTR + col)*4, Vb + (size_t)row*MM + col);
    }
    asm volatile("cp.async.commit_group;");

    for (int jt = 0; jt < 16; jt++) {
        int buf = jt & 1;
        if (jt < 15) {
            int nb = buf ^ 1;
            const float* qg = Qb + (size_t)(jt+1)*64*DD;
            const float* vg = Vb + (jt+1)*64;
            #pragma unroll
            for (int k = 0; k < 4; k++) {
                int l = 4*tid + 1024*k;
                int row = l >> 6, col = l & 63;
                cp16(qbase[nb] + (row*TSTR + col)*4, qg + (size_t)row*DD + col);
                cp16(vbase[nb] + (row*TSTR + col)*4, vg + (size_t)row*MM + col);
            }
            asm volatile("cp.async.commit_group;");
            asm volatile("cp.async.wait_group 1;");
        } else {
            asm volatile("cp.async.wait_group 0;");
        }
        __syncthreads();

        const float* Qc = Qs[buf];
        const float* Vc = Vs[buf];

        // ---- S = K . Q^T  (B-frags: one float4 = 2 k-steps) ----
        float s[8][4];
        #pragma unroll
        for (int nt = 0; nt < 8; nt++) {
            s[nt][0] = s[nt][1] = s[nt][2] = s[nt][3] = 0.f;
            const float* qrow = &Qc[(nt*8 + qr)*TSTR + qc*16];
            #pragma unroll
            for (int kkp = 0; kkp < 4; kkp++) {
                float4 f = *(const float4*)&qrow[4*kkp];
                mma_tf32(s[nt][0], s[nt][1], s[nt][2], s[nt][3],
                         ka[2*kkp][0], ka[2*kkp][1], ka[2*kkp][2], ka[2*kkp][3],
                         __float_as_uint(f.x), __float_as_uint(f.y));
                mma_tf32(s[nt][0], s[nt][1], s[nt][2], s[nt][3],
                         ka[2*kkp+1][0], ka[2*kkp+1][1], ka[2*kkp+1][2], ka[2*kkp+1][3],
                         __float_as_uint(f.z), __float_as_uint(f.w));
            }
        }

        // ---- leaky relu + online softmax ----
        float m0 = -1e30f, m1 = -1e30f;
        #pragma unroll
        for (int nt = 0; nt < 8; nt++) {
            #pragma unroll
            for (int c = 0; c < 4; c++)
                s[nt][c] = s[nt][c] > 0.f ? s[nt][c] : NEG*s[nt][c];
            m0 = fmaxf(m0, fmaxf(s[nt][0], s[nt][1]));
            m1 = fmaxf(m1, fmaxf(s[nt][2], s[nt][3]));
        }
        m0 = fmaxf(m0, __shfl_xor_sync(0xffffffffu, m0, 1));
        m0 = fmaxf(m0, __shfl_xor_sync(0xffffffffu, m0, 2));
        m1 = fmaxf(m1, __shfl_xor_sync(0xffffffffu, m1, 1));
        m1 = fmaxf(m1, __shfl_xor_sync(0xffffffffu, m1, 2));
        float nm0 = fmaxf(mr0, m0), nm1 = fmaxf(mr1, m1);
        float c0 = __expf(mr0 - nm0), c1 = __expf(mr1 - nm1);
        mr0 = nm0; mr1 = nm1;
        float a0 = 0.f, a1 = 0.f;
        #pragma unroll
        for (int nt = 0; nt < 8; nt++) {
            s[nt][0] = __expf(s[nt][0] - nm0);
            s[nt][1] = __expf(s[nt][1] - nm0);
            s[nt][2] = __expf(s[nt][2] - nm1);
            s[nt][3] = __expf(s[nt][3] - nm1);
            a0 += s[nt][0] + s[nt][1];
            a1 += s[nt][2] + s[nt][3];
            o[nt][0] *= c0; o[nt][1] *= c0; o[nt][2] *= c1; o[nt][3] *= c1;
        }
        a0 += __shfl_xor_sync(0xffffffffu, a0, 1);
        a0 += __shfl_xor_sync(0xffffffffu, a0, 2);
        a1 += __shfl_xor_sync(0xffffffffu, a1, 1);
        a1 += __shfl_xor_sync(0xffffffffu, a1, 2);
        lr0 = lr0*c0 + a0;
        lr1 = lr1*c1 + a1;

        // ---- O += P . V  (A-frags from s registers; V rows j-permuted) ----
        #pragma unroll
        for (int kkp = 0; kkp < 4; kkp++) {
            int k0 = 2*kkp, k1 = 2*kkp + 1;
            unsigned p00 = f2tf32(s[k0][0]), p01 = f2tf32(s[k0][2]);
            unsigned p02 = f2tf32(s[k0][1]), p03 = f2tf32(s[k0][3]);
            unsigned p10 = f2tf32(s[k1][0]), p11 = f2tf32(s[k1][2]);
            unsigned p12 = f2tf32(s[k1][1]), p13 = f2tf32(s[k1][3]);
            #pragma unroll
            for (int nt = 0; nt < 8; nt++) {
                float4 g = *(const float4*)&Vc[(nt*8 + qr)*TSTR + qc*16 + 4*kkp];
                mma_tf32(o[nt][0], o[nt][1], o[nt][2], o[nt][3],
                         p00, p01, p02, p03,
                         __float_as_uint(g.x), __float_as_uint(g.y));
                mma_tf32(o[nt][0], o[nt][1], o[nt][2], o[nt][3],
                         p10, p11, p12, p13,
                         __float_as_uint(g.z), __float_as_uint(g.w));
            }
        }
        __syncthreads();
    }

    // ---- epilogue: leaky(o/l) - x -> g_dx (N, M, H*D) ----
    float inv0 = 1.f / lr0, inv1 = 1.f / lr1;
    size_t gm0 = (size_t)(n*MM + r0);
    size_t gm1 = gm0 + 8;
    const float* x0 = x + gm0*DD;
    const float* x1 = x + gm1*DD;
    float* d0 = g_dx + gm0*(HH*DD) + h*DD;
    float* d1 = g_dx + gm1*(HH*DD) + h*DD;
    #pragma unroll
    for (int nt = 0; nt < 8; nt++) {
        int cb = nt*8 + 2*qc;
        float2 xv0 = *(const float2*)&x0[cb];
        float2 xv1 = *(const float2*)&x1[cb];
        float v00 = o[nt][0]*inv0; v00 = (v00 > 0.f ? v00 : NEG*v00) - xv0.x;
        float v01 = o[nt][1]*inv0; v01 = (v01 > 0.f ? v01 : NEG*v01) - xv0.y;
        float v10 = o[nt][2]*inv1; v10 = (v10 > 0.f ? v10 : NEG*v10) - xv1.x;
        float v11 = o[nt][3]*inv1; v11 = (v11 > 0.f ? v11 : NEG*v11) - xv1.y;
        *(float2*)&d0[cb] = make_float2(v00, v01);
        *(float2*)&d1[cb] = make_float2(v10, v11);
    }
}

// ---------------------------------------------------------------------------
// Kernel 3: decoder (fp32 SIMT).
// ---------------------------------------------------------------------------
#define DEC_SMEM ((64*256 + 64*257) * 4)

__global__ __launch_bounds__(256) void dec_kernel(
    const float* __restrict__ Wdec, const float* __restrict__ bdec,
    float* __restrict__ out)
{
    extern __shared__ float sm[];
    float* ds = sm;
    float* Ws = ds + 64*256;
    int row0 = blockIdx.x * 64;
    int tx = threadIdx.x, ty = threadIdx.y;
    int tid = ty*16 + tx;
    #pragma unroll
    for (int r = 0; r < 64; r++) {
        int l = r*256 + tid;
        ds[l] = g_dx[(size_t)row0*256 + l];
        Ws[(l>>8)*257 + (l&255)] = Wdec[l];
    }
    __syncthreads();
    float acc[4][4] = {};
    int ty4 = ty*4;
    #pragma unroll 4
    for (int c = 0; c < 256; c += 4) {
        float4 dr[4];
        #pragma unroll
        for (int a = 0; a < 4; a++)
            dr[a] = *(const float4*)&ds[(ty4+a)*256 + c];
        #pragma unroll
        for (int b = 0; b < 4; b++) {
            const float* wp = &Ws[(b*16+tx)*257 + c];
            float w0 = wp[0], w1 = wp[1], w2 = wp[2], w3 = wp[3];
            #pragma unroll
            for (int a = 0; a < 4; a++) {
                acc[a][b] = fmaf(dr[a].x, w0, acc[a][b]);
                acc[a][b] = fmaf(dr[a].y, w1, acc[a][b]);
                acc[a][b] = fmaf(dr[a].z, w2, acc[a][b]);
                acc[a][b] = fmaf(dr[a].w, w3, acc[a][b]);
            }
        }
    }
    #pragma unroll
    for (int b = 0; b < 4; b++) {
        float bb = bdec[b*16 + tx];
        #pragma unroll
        for (int a = 0; a < 4; a++)
            out[(size_t)(row0 + ty4 + a)*DD + b*16 + tx] = acc[a][b] + bb;
    }
}

// ---------------------------------------------------------------------------
extern "C" void kernel_launch(void* const* d_in, const int* in_sizes, int n_in,
                              void* d_out, int out_size)
{
    const float* x    = (const float*)d_in[0];
    // d_in[1] = edge (unused)
    const float* Wk   = (const float*)d_in[2];
    const float* bk   = (const float*)d_in[3];
    const float* Wq   = (const float*)d_in[4];
    const float* bq   = (const float*)d_in[5];
    const float* Wv   = (const float*)d_in[6];
    const float* bv   = (const float*)d_in[7];
    const float* Wdec = (const float*)d_in[8];
    const float* bdec = (const float*)d_in[9];
    float* out = (float*)d_out;

    cudaFuncSetAttribute(attn_tc,    cudaFuncAttributeMaxDynamicSharedMemorySize, ATTN2_SMEM);
    cudaFuncSetAttribute(dec_kernel, cudaFuncAttributeMaxDynamicSharedMemorySize, DEC_SMEM);

    qkv_tc<<<dim3(MM/128, 3*HH, NB), 256>>>(x, Wk, bk, Wq, bq, Wv, bv);
    attn_tc<<<dim3(MM/128, HH, NB), 256, ATTN2_SMEM>>>(x);
    dec_kernel<<<NB*MM/64, dim3(16,16), DEC_SMEM>>>(Wdec, bdec, out);
}